// round 15
// baseline (speedup 1.0000x reference)
#include <cuda_runtime.h>
#include <cuda_fp16.h>
#include <cstdint>

#define IDIM 1024
#define ODIM 1024
#define NDEG 9
#define KG 8192            // GEMM K (Chebyshev j = 1..8); T0 handled as bias
#define BMAX 8192

// ---------------- device scratch (static globals: allocation-guard safe) ----
__device__ __half g_A[(size_t)BMAX * KG];   // T basis fp16, k = (j-1)*1024 + i
__device__ __half g_B[(size_t)ODIM * KG];   // coeffs fp16,  [o][k]
__device__ float g_bias[ODIM];

// ---------------------------------------------------------------------------
// Kernel 1: fused row min/max + Chebyshev basis -> fp16
// ---------------------------------------------------------------------------
__global__ void __launch_bounds__(256) buildT_kernel(const float* __restrict__ x) {
    const int b = blockIdx.x;
    const int tid = threadIdx.x;
    const float* row = x + (size_t)b * IDIM;

    float2 v[2];
    #pragma unroll
    for (int s = 0; s < 2; s++)
        v[s] = *(const float2*)(row + 2 * (tid + 256 * s));

    float mn = fminf(fminf(v[0].x, v[0].y), fminf(v[1].x, v[1].y));
    float mx = fmaxf(fmaxf(v[0].x, v[0].y), fmaxf(v[1].x, v[1].y));
    #pragma unroll
    for (int o = 16; o; o >>= 1) {
        mn = fminf(mn, __shfl_xor_sync(0xFFFFFFFFu, mn, o));
        mx = fmaxf(mx, __shfl_xor_sync(0xFFFFFFFFu, mx, o));
    }
    __shared__ float smn[8], smx[8];
    int w = tid >> 5, l = tid & 31;
    if (l == 0) { smn[w] = mn; smx[w] = mx; }
    __syncthreads();
    #pragma unroll
    for (int i = 0; i < 8; i++) { mn = fminf(mn, smn[i]); mx = fmaxf(mx, smx[i]); }
    const float sc = 2.0f / (mx - mn);

    const size_t base = (size_t)b * KG;
    #pragma unroll
    for (int s = 0; s < 2; s++) {
        int p = tid + 256 * s;
        float xa = (v[s].x - mn) * sc - 1.0f;
        float xb = (v[s].y - mn) * sc - 1.0f;
        float a0 = 1.0f, a1 = xa, b0 = 1.0f, b1 = xb;
        #pragma unroll
        for (int j = 1; j < NDEG; j++) {
            __half2 h2;
            h2.x = __float2half_rn(a1);
            h2.y = __float2half_rn(b1);
            *(__half2*)(g_A + base + (size_t)(j - 1) * IDIM + 2 * p) = h2;
            float na = 2.0f * xa * a1 - a0; a0 = a1; a1 = na;
            float nb = 2.0f * xb * b1 - b0; b0 = b1; b1 = nb;
        }
    }
}

// ---------------------------------------------------------------------------
// Kernel 2: coeffs -> B fp16 (k=(j-1)*1024+i) + bias[o] fused
// ---------------------------------------------------------------------------
__global__ void __launch_bounds__(256) transC_kernel(const float* __restrict__ c) {
    const int o = blockIdx.x;
    const int tid = threadIdx.x;
    float bsum = 0.0f;
    #pragma unroll
    for (int s = 0; s < 4; s++) {
        int i = tid + 256 * s;
        const float* src = c + ((size_t)i * ODIM + o) * NDEG;
        bsum += src[0];
        #pragma unroll
        for (int j = 1; j < NDEG; j++)
            g_B[(size_t)o * KG + (size_t)(j - 1) * IDIM + i] = __float2half_rn(src[j]);
    }
    #pragma unroll
    for (int w = 16; w; w >>= 1) bsum += __shfl_xor_sync(0xFFFFFFFFu, bsum, w);
    __shared__ float sh[8];
    if ((tid & 31) == 0) sh[tid >> 5] = bsum;
    __syncthreads();
    if (tid == 0) {
        float t = 0.0f;
        #pragma unroll
        for (int i = 0; i < 8; i++) t += sh[i];
        g_bias[o] = t;
    }
}

// ---------------------------------------------------------------------------
// Kernel 3: fp16 GEMM, CTA 128x128, 256 thr, warp 32x64, 3-stage ring.
// f16 accumulation within each K=64 chunk, promoted to f32 once per chunk.
// ---------------------------------------------------------------------------
#define TILE_M 128
#define TILE_N 128
#define NQG (KG / 64)               // 128 stages of 64 elems
#define ROWPB 144
#define A_ST (TILE_M * ROWPB)       // 18432
#define B_ST (TILE_N * ROWPB)       // 18432
#define STAGE (A_ST + B_ST)         // 36864
#define SMEM_TOTAL (3 * STAGE)      // 110592

__device__ __forceinline__ uint32_t smem_u32(const void* p) {
    uint32_t a;
    asm("{ .reg .u64 t; cvta.to.shared.u64 t, %1; cvt.u32.u64 %0, t; }"
        : "=r"(a) : "l"(p));
    return a;
}
__device__ __forceinline__ void cp16(uint32_t dst, const void* src) {
    asm volatile("cp.async.cg.shared.global [%0], [%1], 16;" :: "r"(dst), "l"(src));
}
__device__ __forceinline__ void ldmx4(uint32_t* r, uint32_t addr) {
    asm volatile("ldmatrix.sync.aligned.m8n8.x4.shared.b16 {%0,%1,%2,%3}, [%4];"
                 : "=r"(r[0]), "=r"(r[1]), "=r"(r[2]), "=r"(r[3]) : "r"(addr));
}
// f16-accumulator HMMA: 2 output regs (4 halves)
__device__ __forceinline__ void mma_f16acc(uint32_t* c, const uint32_t* a, const uint32_t* b) {
    asm volatile(
        "mma.sync.aligned.m16n8k16.row.col.f16.f16.f16.f16 "
        "{%0,%1}, {%2,%3,%4,%5}, {%6,%7}, {%0,%1};"
        : "+r"(c[0]), "+r"(c[1])
        : "r"(a[0]), "r"(a[1]), "r"(a[2]), "r"(a[3]), "r"(b[0]), "r"(b[1]));
}

extern __shared__ char dynsmem[];

__global__ void __launch_bounds__(256, 1) gemm_kernel(float* __restrict__ out) {
    const uint32_t smem_base = smem_u32(dynsmem);
    const int tid = threadIdx.x;
    const int lane = tid & 31;
    const int warp = tid >> 5;
    const int wm = warp & 3;         // M band: 32*wm
    const int wn = warp >> 2;        // N band: 64*wn

    const int mBase = blockIdx.y * TILE_M;
    const int nBase = blockIdx.x * TILE_N;

    const __half* Ag = g_A + (size_t)mBase * KG;
    const __half* Bg = g_B + (size_t)nBase * KG;

    const int aRow = (lane & 7) + ((lane >> 3) & 1) * 8;
    const int aK8  = (lane >> 4) & 1;
    const int bRow = (lane & 7) + ((lane >> 4) & 1) * 8;
    const int bK8  = (lane >> 3) & 1;

    float acc[2][8][4];
    #pragma unroll
    for (int mt = 0; mt < 2; mt++)
        #pragma unroll
        for (int nt = 0; nt < 8; nt++)
            #pragma unroll
            for (int j = 0; j < 4; j++)
                acc[mt][nt][j] = 0.0f;

    auto load_stage = [&](int q, int buf) {
        const int k0 = q * 64;
        const uint32_t so = smem_base + buf * STAGE;
        #pragma unroll
        for (int r = 0; r < 4; r++) {
            int c = tid + 256 * r;
            int row = c >> 3, c16 = c & 7;
            cp16(so + row * ROWPB + c16 * 16,
                 Ag + (size_t)row * KG + k0 + c16 * 8);
        }
        #pragma unroll
        for (int r = 0; r < 4; r++) {
            int c = tid + 256 * r;
            int row = c >> 3, c16 = c & 7;
            cp16(so + A_ST + row * ROWPB + c16 * 16,
                 Bg + (size_t)row * KG + k0 + c16 * 8);
        }
        asm volatile("cp.async.commit_group;" ::: "memory");
    };

    load_stage(0, 0);
    load_stage(1, 1);

    for (int q = 0; q < NQG; q++) {
        if (q + 1 < NQG)
            asm volatile("cp.async.wait_group 1;" ::: "memory");
        else
            asm volatile("cp.async.wait_group 0;" ::: "memory");
        __syncthreads();
        if (q + 2 < NQG)
            load_stage(q + 2, (q + 2) % 3);

        const uint32_t so = smem_base + (q % 3) * STAGE;
        const uint32_t aBase = so + (wm * 32 + aRow) * ROWPB + aK8 * 16;
        const uint32_t bBase = so + A_ST + (wn * 64 + bRow) * ROWPB + bK8 * 16;

        // f16 chunk accumulators (zeroed per K=64 chunk)
        uint32_t c16[2][8][2];
        #pragma unroll
        for (int mt = 0; mt < 2; mt++)
            #pragma unroll
            for (int nt = 0; nt < 8; nt++)
                { c16[mt][nt][0] = 0u; c16[mt][nt][1] = 0u; }

        #pragma unroll
        for (int kk = 0; kk < 64; kk += 16) {
            uint32_t af[2][4];
            uint32_t bf[8][2];
            #pragma unroll
            for (int mt = 0; mt < 2; mt++)
                ldmx4(af[mt], aBase + mt * 16 * ROWPB + kk * 2);
            #pragma unroll
            for (int nt2 = 0; nt2 < 4; nt2++) {
                uint32_t r[4];
                ldmx4(r, bBase + nt2 * 16 * ROWPB + kk * 2);
                bf[nt2*2+0][0] = r[0]; bf[nt2*2+0][1] = r[1];
                bf[nt2*2+1][0] = r[2]; bf[nt2*2+1][1] = r[3];
            }
            #pragma unroll
            for (int mt = 0; mt < 2; mt++)
                #pragma unroll
                for (int nt = 0; nt < 8; nt++)
                    mma_f16acc(c16[mt][nt], af[mt], bf[nt]);
        }

        // promote chunk sums to f32 accumulators
        #pragma unroll
        for (int mt = 0; mt < 2; mt++)
            #pragma unroll
            for (int nt = 0; nt < 8; nt++) {
                float2 f0 = __half22float2(*(__half2*)&c16[mt][nt][0]);
                float2 f1 = __half22float2(*(__half2*)&c16[mt][nt][1]);
                acc[mt][nt][0] += f0.x;
                acc[mt][nt][1] += f0.y;
                acc[mt][nt][2] += f1.x;
                acc[mt][nt][3] += f1.y;
            }
    }

    // epilogue: out = acc + bias
    const int mW = mBase + wm * 32;
    const int nW = nBase + wn * 64;
    #pragma unroll
    for (int mt = 0; mt < 2; mt++) {
        #pragma unroll
        for (int nt = 0; nt < 8; nt++) {
            int row0 = mW + mt * 16 + (lane >> 2);
            int col  = nW + nt * 8 + (lane & 3) * 2;
            float b0 = g_bias[col], b1 = g_bias[col + 1];
            *(float2*)(out + (size_t)row0 * ODIM + col) =
                make_float2(acc[mt][nt][0] + b0, acc[mt][nt][1] + b1);
            *(float2*)(out + (size_t)(row0 + 8) * ODIM + col) =
                make_float2(acc[mt][nt][2] + b0, acc[mt][nt][3] + b1);
        }
    }
}

// ---------------------------------------------------------------------------
extern "C" void kernel_launch(void* const* d_in, const int* in_sizes, int n_in,
                              void* d_out, int out_size) {
    const float* x = (const float*)d_in[0];
    const float* coeffs = (const float*)d_in[1];
    float* out = (float*)d_out;

    int nb = in_sizes[0] / IDIM;   // 8192

    cudaFuncSetAttribute(gemm_kernel,
                         cudaFuncAttributeMaxDynamicSharedMemorySize, SMEM_TOTAL);

    buildT_kernel<<<nb, 256>>>(x);
    transC_kernel<<<ODIM, 256>>>(coeffs);

    dim3 grid(ODIM / TILE_N, nb / TILE_M);   // (8, 64) = 512 CTAs
    gemm_kernel<<<grid, 256, SMEM_TOTAL>>>(out);
}

// round 16
// speedup vs baseline: 1.3116x; 1.3116x over previous
#include <cuda_runtime.h>
#include <cuda_fp16.h>
#include <cstdint>

#define IDIM 1024
#define ODIM 1024
#define NDEG 9
#define KG 8192            // GEMM K (Chebyshev j = 1..8); T0 handled as bias
#define BMAX 8192

// ---------------- device scratch (static globals: allocation-guard safe) ----
__device__ __half g_A[(size_t)BMAX * KG];   // T basis fp16, k = (j-1)*1024 + i
__device__ __half g_B[(size_t)ODIM * KG];   // coeffs fp16,  [o][k]
__device__ float g_bias[ODIM];

// ---------------------------------------------------------------------------
// Kernel 1: fused row min/max + Chebyshev basis -> fp16
// ---------------------------------------------------------------------------
__global__ void __launch_bounds__(256) buildT_kernel(const float* __restrict__ x) {
    const int b = blockIdx.x;
    const int tid = threadIdx.x;
    const float* row = x + (size_t)b * IDIM;

    float2 v[2];
    #pragma unroll
    for (int s = 0; s < 2; s++)
        v[s] = *(const float2*)(row + 2 * (tid + 256 * s));

    float mn = fminf(fminf(v[0].x, v[0].y), fminf(v[1].x, v[1].y));
    float mx = fmaxf(fmaxf(v[0].x, v[0].y), fmaxf(v[1].x, v[1].y));
    #pragma unroll
    for (int o = 16; o; o >>= 1) {
        mn = fminf(mn, __shfl_xor_sync(0xFFFFFFFFu, mn, o));
        mx = fmaxf(mx, __shfl_xor_sync(0xFFFFFFFFu, mx, o));
    }
    __shared__ float smn[8], smx[8];
    int w = tid >> 5, l = tid & 31;
    if (l == 0) { smn[w] = mn; smx[w] = mx; }
    __syncthreads();
    #pragma unroll
    for (int i = 0; i < 8; i++) { mn = fminf(mn, smn[i]); mx = fmaxf(mx, smx[i]); }
    const float sc = 2.0f / (mx - mn);

    const size_t base = (size_t)b * KG;
    #pragma unroll
    for (int s = 0; s < 2; s++) {
        int p = tid + 256 * s;
        float xa = (v[s].x - mn) * sc - 1.0f;
        float xb = (v[s].y - mn) * sc - 1.0f;
        float a0 = 1.0f, a1 = xa, b0 = 1.0f, b1 = xb;
        #pragma unroll
        for (int j = 1; j < NDEG; j++) {
            __half2 h2;
            h2.x = __float2half_rn(a1);
            h2.y = __float2half_rn(b1);
            *(__half2*)(g_A + base + (size_t)(j - 1) * IDIM + 2 * p) = h2;
            float na = 2.0f * xa * a1 - a0; a0 = a1; a1 = na;
            float nb = 2.0f * xb * b1 - b0; b0 = b1; b1 = nb;
        }
    }
}

// ---------------------------------------------------------------------------
// Kernel 2: coeffs -> B fp16 (k=(j-1)*1024+i) + bias[o] fused
// ---------------------------------------------------------------------------
__global__ void __launch_bounds__(256) transC_kernel(const float* __restrict__ c) {
    const int o = blockIdx.x;
    const int tid = threadIdx.x;
    float bsum = 0.0f;
    #pragma unroll
    for (int s = 0; s < 4; s++) {
        int i = tid + 256 * s;
        const float* src = c + ((size_t)i * ODIM + o) * NDEG;
        bsum += src[0];
        #pragma unroll
        for (int j = 1; j < NDEG; j++)
            g_B[(size_t)o * KG + (size_t)(j - 1) * IDIM + i] = __float2half_rn(src[j]);
    }
    #pragma unroll
    for (int w = 16; w; w >>= 1) bsum += __shfl_xor_sync(0xFFFFFFFFu, bsum, w);
    __shared__ float sh[8];
    if ((tid & 31) == 0) sh[tid >> 5] = bsum;
    __syncthreads();
    if (tid == 0) {
        float t = 0.0f;
        #pragma unroll
        for (int i = 0; i < 8; i++) t += sh[i];
        g_bias[o] = t;
    }
}

// ---------------------------------------------------------------------------
// Kernel 3: fp16 GEMM, CTA 128x128, 256 thr, warp 32x64, 3-stage, 2 CTAs/SM
// (byte-identical to R14's proven 435us config)
// ---------------------------------------------------------------------------
#define TILE_M 128
#define TILE_N 128
#define NQG (KG / 64)               // 128 stages of 64 elems
#define ROWPB 144
#define A_ST (TILE_M * ROWPB)       // 18432
#define B_ST (TILE_N * ROWPB)       // 18432
#define STAGE (A_ST + B_ST)         // 36864
#define SMEM_TOTAL (3 * STAGE)      // 110592 per CTA -> 2 CTAs = 221184/SM

__device__ __forceinline__ uint32_t smem_u32(const void* p) {
    uint32_t a;
    asm("{ .reg .u64 t; cvta.to.shared.u64 t, %1; cvt.u32.u64 %0, t; }"
        : "=r"(a) : "l"(p));
    return a;
}
__device__ __forceinline__ void cp16(uint32_t dst, const void* src) {
    asm volatile("cp.async.cg.shared.global [%0], [%1], 16;" :: "r"(dst), "l"(src));
}
__device__ __forceinline__ void ldmx4(uint32_t* r, uint32_t addr) {
    asm volatile("ldmatrix.sync.aligned.m8n8.x4.shared.b16 {%0,%1,%2,%3}, [%4];"
                 : "=r"(r[0]), "=r"(r[1]), "=r"(r[2]), "=r"(r[3]) : "r"(addr));
}
__device__ __forceinline__ void mma_f16(float* c, const uint32_t* a, const uint32_t* b) {
    asm volatile(
        "mma.sync.aligned.m16n8k16.row.col.f32.f16.f16.f32 "
        "{%0,%1,%2,%3}, {%4,%5,%6,%7}, {%8,%9}, {%0,%1,%2,%3};"
        : "+f"(c[0]), "+f"(c[1]), "+f"(c[2]), "+f"(c[3])
        : "r"(a[0]), "r"(a[1]), "r"(a[2]), "r"(a[3]), "r"(b[0]), "r"(b[1]));
}

extern __shared__ char dynsmem[];

__global__ void __launch_bounds__(256, 2) gemm_kernel(float* __restrict__ out) {
    const uint32_t smem_base = smem_u32(dynsmem);
    const int tid = threadIdx.x;
    const int lane = tid & 31;
    const int warp = tid >> 5;
    const int wm = warp & 3;         // M band: 32*wm
    const int wn = warp >> 2;        // N band: 64*wn

    const int mBase = blockIdx.y * TILE_M;
    const int nBase = blockIdx.x * TILE_N;

    const __half* Ag = g_A + (size_t)mBase * KG;
    const __half* Bg = g_B + (size_t)nBase * KG;

    const int aRow = (lane & 7) + ((lane >> 3) & 1) * 8;
    const int aK8  = (lane >> 4) & 1;
    const int bRow = (lane & 7) + ((lane >> 4) & 1) * 8;
    const int bK8  = (lane >> 3) & 1;

    float acc[2][8][4];
    #pragma unroll
    for (int mt = 0; mt < 2; mt++)
        #pragma unroll
        for (int nt = 0; nt < 8; nt++)
            #pragma unroll
            for (int j = 0; j < 4; j++)
                acc[mt][nt][j] = 0.0f;

    auto load_stage = [&](int q, int buf) {
        const int k0 = q * 64;
        const uint32_t so = smem_base + buf * STAGE;
        #pragma unroll
        for (int r = 0; r < 4; r++) {
            int c = tid + 256 * r;
            int row = c >> 3, c16 = c & 7;
            cp16(so + row * ROWPB + c16 * 16,
                 Ag + (size_t)row * KG + k0 + c16 * 8);
        }
        #pragma unroll
        for (int r = 0; r < 4; r++) {
            int c = tid + 256 * r;
            int row = c >> 3, c16 = c & 7;
            cp16(so + A_ST + row * ROWPB + c16 * 16,
                 Bg + (size_t)row * KG + k0 + c16 * 8);
        }
        asm volatile("cp.async.commit_group;" ::: "memory");
    };

    load_stage(0, 0);
    load_stage(1, 1);

    for (int q = 0; q < NQG; q++) {
        if (q + 1 < NQG)
            asm volatile("cp.async.wait_group 1;" ::: "memory");
        else
            asm volatile("cp.async.wait_group 0;" ::: "memory");
        __syncthreads();
        // barrier guarantees buffer (q+2)%3 (== (q-1)%3) is no longer read
        if (q + 2 < NQG)
            load_stage(q + 2, (q + 2) % 3);

        const uint32_t so = smem_base + (q % 3) * STAGE;
        const uint32_t aBase = so + (wm * 32 + aRow) * ROWPB + aK8 * 16;
        const uint32_t bBase = so + A_ST + (wn * 64 + bRow) * ROWPB + bK8 * 16;

        #pragma unroll
        for (int kk = 0; kk < 64; kk += 16) {
            uint32_t af[2][4];
            uint32_t bf[8][2];
            #pragma unroll
            for (int mt = 0; mt < 2; mt++)
                ldmx4(af[mt], aBase + mt * 16 * ROWPB + kk * 2);
            #pragma unroll
            for (int nt2 = 0; nt2 < 4; nt2++) {
                uint32_t r[4];
                ldmx4(r, bBase + nt2 * 16 * ROWPB + kk * 2);
                bf[nt2*2+0][0] = r[0]; bf[nt2*2+0][1] = r[1];
                bf[nt2*2+1][0] = r[2]; bf[nt2*2+1][1] = r[3];
            }
            #pragma unroll
            for (int mt = 0; mt < 2; mt++)
                #pragma unroll
                for (int nt = 0; nt < 8; nt++)
                    mma_f16(acc[mt][nt], af[mt], bf[nt]);
        }
    }

    // epilogue: out = acc + bias
    const int mW = mBase + wm * 32;
    const int nW = nBase + wn * 64;
    #pragma unroll
    for (int mt = 0; mt < 2; mt++) {
        #pragma unroll
        for (int nt = 0; nt < 8; nt++) {
            int row0 = mW + mt * 16 + (lane >> 2);
            int col  = nW + nt * 8 + (lane & 3) * 2;
            float b0 = g_bias[col], b1 = g_bias[col + 1];
            *(float2*)(out + (size_t)row0 * ODIM + col) =
                make_float2(acc[mt][nt][0] + b0, acc[mt][nt][1] + b1);
            *(float2*)(out + (size_t)(row0 + 8) * ODIM + col) =
                make_float2(acc[mt][nt][2] + b0, acc[mt][nt][3] + b1);
        }
    }
}

// ---------------------------------------------------------------------------
// Launch: fork buildT / transC onto two streams (independent), join for GEMM.
// Event fork/join is the documented graph-capture-legal multi-stream pattern.
// ---------------------------------------------------------------------------
extern "C" void kernel_launch(void* const* d_in, const int* in_sizes, int n_in,
                              void* d_out, int out_size) {
    const float* x = (const float*)d_in[0];
    const float* coeffs = (const float*)d_in[1];
    float* out = (float*)d_out;

    int nb = in_sizes[0] / IDIM;   // 8192

    static cudaStream_t s1 = nullptr, s2 = nullptr;
    static cudaEvent_t eFork = nullptr, e1 = nullptr, e2 = nullptr;
    static bool init_done = false;
    if (!init_done) {
        cudaFuncSetAttribute(gemm_kernel,
                             cudaFuncAttributeMaxDynamicSharedMemorySize, SMEM_TOTAL);
        cudaStreamCreateWithFlags(&s1, cudaStreamNonBlocking);
        cudaStreamCreateWithFlags(&s2, cudaStreamNonBlocking);
        cudaEventCreateWithFlags(&eFork, cudaEventDisableTiming);
        cudaEventCreateWithFlags(&e1, cudaEventDisableTiming);
        cudaEventCreateWithFlags(&e2, cudaEventDisableTiming);
        init_done = true;
    }

    // fork from the launch (legacy) stream
    cudaEventRecord(eFork, 0);
    cudaStreamWaitEvent(s1, eFork, 0);
    cudaStreamWaitEvent(s2, eFork, 0);

    buildT_kernel<<<nb, 256, 0, s1>>>(x);
    cudaEventRecord(e1, s1);

    transC_kernel<<<ODIM, 256, 0, s2>>>(coeffs);
    cudaEventRecord(e2, s2);

    // join back onto the launch stream
    cudaStreamWaitEvent(0, e1, 0);
    cudaStreamWaitEvent(0, e2, 0);

    dim3 grid(ODIM / TILE_N, nb / TILE_M);   // (8, 64) = 512 CTAs
    gemm_kernel<<<grid, 256, SMEM_TOTAL>>>(out);
}

// round 17
// speedup vs baseline: 1.3508x; 1.0299x over previous
#include <cuda_runtime.h>
#include <cuda_fp16.h>
#include <cstdint>

#define IDIM 1024
#define ODIM 1024
#define NDEG 9
#define KG 8192            // GEMM K (Chebyshev j = 1..8); T0 handled as bias
#define BMAX 8192

// ---------------- device scratch (static globals: allocation-guard safe) ----
__device__ __half g_A[(size_t)BMAX * KG];   // T basis fp16, k = (j-1)*1024 + i
__device__ __half g_B[(size_t)ODIM * KG];   // coeffs fp16,  [o][k]
__device__ float g_bias[ODIM];

// ---------------------------------------------------------------------------
// Fused preprocessing: blocks [0,1024) do transC+bias for o=blockIdx;
// blocks [1024, 1024+8192) do buildT for b = blockIdx-1024.
// transC first so its blocks co-run under the memory-bound buildT stream.
// ---------------------------------------------------------------------------
__global__ void __launch_bounds__(256) prep_kernel(const float* __restrict__ x,
                                                   const float* __restrict__ c) {
    const int tid = threadIdx.x;

    if (blockIdx.x < ODIM) {
        // ---- transC + bias for output column o ----
        const int o = blockIdx.x;
        float bsum = 0.0f;
        #pragma unroll
        for (int s = 0; s < 4; s++) {
            int i = tid + 256 * s;
            const float* src = c + ((size_t)i * ODIM + o) * NDEG;
            bsum += src[0];
            #pragma unroll
            for (int j = 1; j < NDEG; j++)
                g_B[(size_t)o * KG + (size_t)(j - 1) * IDIM + i] = __float2half_rn(src[j]);
        }
        #pragma unroll
        for (int w = 16; w; w >>= 1) bsum += __shfl_xor_sync(0xFFFFFFFFu, bsum, w);
        __shared__ float sh[8];
        if ((tid & 31) == 0) sh[tid >> 5] = bsum;
        __syncthreads();
        if (tid == 0) {
            float t = 0.0f;
            #pragma unroll
            for (int i = 0; i < 8; i++) t += sh[i];
            g_bias[o] = t;
        }
        return;
    }

    // ---- buildT for batch row b ----
    const int b = blockIdx.x - ODIM;
    const float* row = x + (size_t)b * IDIM;

    float2 v[2];
    #pragma unroll
    for (int s = 0; s < 2; s++)
        v[s] = *(const float2*)(row + 2 * (tid + 256 * s));

    float mn = fminf(fminf(v[0].x, v[0].y), fminf(v[1].x, v[1].y));
    float mx = fmaxf(fmaxf(v[0].x, v[0].y), fmaxf(v[1].x, v[1].y));
    #pragma unroll
    for (int o = 16; o; o >>= 1) {
        mn = fminf(mn, __shfl_xor_sync(0xFFFFFFFFu, mn, o));
        mx = fmaxf(mx, __shfl_xor_sync(0xFFFFFFFFu, mx, o));
    }
    __shared__ float smn[8], smx[8];
    int w = tid >> 5, l = tid & 31;
    if (l == 0) { smn[w] = mn; smx[w] = mx; }
    __syncthreads();
    #pragma unroll
    for (int i = 0; i < 8; i++) { mn = fminf(mn, smn[i]); mx = fmaxf(mx, smx[i]); }
    const float sc = 2.0f / (mx - mn);

    const size_t base = (size_t)b * KG;
    #pragma unroll
    for (int s = 0; s < 2; s++) {
        int p = tid + 256 * s;
        float xa = (v[s].x - mn) * sc - 1.0f;
        float xb = (v[s].y - mn) * sc - 1.0f;
        float a0 = 1.0f, a1 = xa, b0 = 1.0f, b1 = xb;
        #pragma unroll
        for (int j = 1; j < NDEG; j++) {
            __half2 h2;
            h2.x = __float2half_rn(a1);
            h2.y = __float2half_rn(b1);
            *(__half2*)(g_A + base + (size_t)(j - 1) * IDIM + 2 * p) = h2;
            float na = 2.0f * xa * a1 - a0; a0 = a1; a1 = na;
            float nb = 2.0f * xb * b1 - b0; b0 = b1; b1 = nb;
        }
    }
}

// ---------------------------------------------------------------------------
// fp16 GEMM, CTA 128x128, 256 thr, warp 32x64, 3-stage ring, 2 CTAs/SM
// (byte-identical mainloop to R14's proven 435us config)
// ---------------------------------------------------------------------------
#define TILE_M 128
#define TILE_N 128
#define NQG (KG / 64)               // 128 stages of 64 elems
#define ROWPB 144
#define A_ST (TILE_M * ROWPB)       // 18432
#define B_ST (TILE_N * ROWPB)       // 18432
#define STAGE (A_ST + B_ST)         // 36864
#define SMEM_TOTAL (3 * STAGE)      // 110592 per CTA -> 2 CTAs = 221184/SM

__device__ __forceinline__ uint32_t smem_u32(const void* p) {
    uint32_t a;
    asm("{ .reg .u64 t; cvta.to.shared.u64 t, %1; cvt.u32.u64 %0, t; }"
        : "=r"(a) : "l"(p));
    return a;
}
__device__ __forceinline__ void cp16(uint32_t dst, const void* src) {
    asm volatile("cp.async.cg.shared.global [%0], [%1], 16;" :: "r"(dst), "l"(src));
}
__device__ __forceinline__ void ldmx4(uint32_t* r, uint32_t addr) {
    asm volatile("ldmatrix.sync.aligned.m8n8.x4.shared.b16 {%0,%1,%2,%3}, [%4];"
                 : "=r"(r[0]), "=r"(r[1]), "=r"(r[2]), "=r"(r[3]) : "r"(addr));
}
__device__ __forceinline__ void mma_f16(float* c, const uint32_t* a, const uint32_t* b) {
    asm volatile(
        "mma.sync.aligned.m16n8k16.row.col.f32.f16.f16.f32 "
        "{%0,%1,%2,%3}, {%4,%5,%6,%7}, {%8,%9}, {%0,%1,%2,%3};"
        : "+f"(c[0]), "+f"(c[1]), "+f"(c[2]), "+f"(c[3])
        : "r"(a[0]), "r"(a[1]), "r"(a[2]), "r"(a[3]), "r"(b[0]), "r"(b[1]));
}

extern __shared__ char dynsmem[];

__global__ void __launch_bounds__(256, 2) gemm_kernel(float* __restrict__ out) {
    const uint32_t smem_base = smem_u32(dynsmem);
    const int tid = threadIdx.x;
    const int lane = tid & 31;
    const int warp = tid >> 5;
    const int wm = warp & 3;         // M band: 32*wm
    const int wn = warp >> 2;        // N band: 64*wn

    const int mBase = blockIdx.y * TILE_M;
    const int nBase = blockIdx.x * TILE_N;

    const __half* Ag = g_A + (size_t)mBase * KG;
    const __half* Bg = g_B + (size_t)nBase * KG;

    const int aRow = (lane & 7) + ((lane >> 3) & 1) * 8;
    const int aK8  = (lane >> 4) & 1;
    const int bRow = (lane & 7) + ((lane >> 4) & 1) * 8;
    const int bK8  = (lane >> 3) & 1;

    float acc[2][8][4];
    #pragma unroll
    for (int mt = 0; mt < 2; mt++)
        #pragma unroll
        for (int nt = 0; nt < 8; nt++)
            #pragma unroll
            for (int j = 0; j < 4; j++)
                acc[mt][nt][j] = 0.0f;

    auto load_stage = [&](int q, int buf) {
        const int k0 = q * 64;
        const uint32_t so = smem_base + buf * STAGE;
        #pragma unroll
        for (int r = 0; r < 4; r++) {
            int c = tid + 256 * r;
            int row = c >> 3, c16 = c & 7;
            cp16(so + row * ROWPB + c16 * 16,
                 Ag + (size_t)row * KG + k0 + c16 * 8);
        }
        #pragma unroll
        for (int r = 0; r < 4; r++) {
            int c = tid + 256 * r;
            int row = c >> 3, c16 = c & 7;
            cp16(so + A_ST + row * ROWPB + c16 * 16,
                 Bg + (size_t)row * KG + k0 + c16 * 8);
        }
        asm volatile("cp.async.commit_group;" ::: "memory");
    };

    load_stage(0, 0);
    load_stage(1, 1);

    for (int q = 0; q < NQG; q++) {
        if (q + 1 < NQG)
            asm volatile("cp.async.wait_group 1;" ::: "memory");
        else
            asm volatile("cp.async.wait_group 0;" ::: "memory");
        __syncthreads();
        // barrier guarantees buffer (q+2)%3 (== (q-1)%3) is no longer read
        if (q + 2 < NQG)
            load_stage(q + 2, (q + 2) % 3);

        const uint32_t so = smem_base + (q % 3) * STAGE;
        const uint32_t aBase = so + (wm * 32 + aRow) * ROWPB + aK8 * 16;
        const uint32_t bBase = so + A_ST + (wn * 64 + bRow) * ROWPB + bK8 * 16;

        #pragma unroll
        for (int kk = 0; kk < 64; kk += 16) {
            uint32_t af[2][4];
            uint32_t bf[8][2];
            #pragma unroll
            for (int mt = 0; mt < 2; mt++)
                ldmx4(af[mt], aBase + mt * 16 * ROWPB + kk * 2);
            #pragma unroll
            for (int nt2 = 0; nt2 < 4; nt2++) {
                uint32_t r[4];
                ldmx4(r, bBase + nt2 * 16 * ROWPB + kk * 2);
                bf[nt2*2+0][0] = r[0]; bf[nt2*2+0][1] = r[1];
                bf[nt2*2+1][0] = r[2]; bf[nt2*2+1][1] = r[3];
            }
            #pragma unroll
            for (int mt = 0; mt < 2; mt++)
                #pragma unroll
                for (int nt = 0; nt < 8; nt++)
                    mma_f16(acc[mt][nt], af[mt], bf[nt]);
        }
    }

    // epilogue: out = acc + bias
    const int mW = mBase + wm * 32;
    const int nW = nBase + wn * 64;
    #pragma unroll
    for (int mt = 0; mt < 2; mt++) {
        #pragma unroll
        for (int nt = 0; nt < 8; nt++) {
            int row0 = mW + mt * 16 + (lane >> 2);
            int col  = nW + nt * 8 + (lane & 3) * 2;
            float b0 = g_bias[col], b1 = g_bias[col + 1];
            *(float2*)(out + (size_t)row0 * ODIM + col) =
                make_float2(acc[mt][nt][0] + b0, acc[mt][nt][1] + b1);
            *(float2*)(out + (size_t)(row0 + 8) * ODIM + col) =
                make_float2(acc[mt][nt][2] + b0, acc[mt][nt][3] + b1);
        }
    }
}

// ---------------------------------------------------------------------------
extern "C" void kernel_launch(void* const* d_in, const int* in_sizes, int n_in,
                              void* d_out, int out_size) {
    const float* x = (const float*)d_in[0];
    const float* coeffs = (const float*)d_in[1];
    float* out = (float*)d_out;

    int nb = in_sizes[0] / IDIM;   // 8192

    static bool init_done = false;
    if (!init_done) {
        cudaFuncSetAttribute(gemm_kernel,
                             cudaFuncAttributeMaxDynamicSharedMemorySize, SMEM_TOTAL);
        init_done = true;
    }

    prep_kernel<<<ODIM + nb, 256>>>(x, coeffs);

    dim3 grid(ODIM / TILE_N, nb / TILE_M);   // (8, 64) = 512 CTAs
    gemm_kernel<<<grid, 256, SMEM_TOTAL>>>(out);
}